// round 16
// baseline (speedup 1.0000x reference)
#include <cuda_runtime.h>
#include <cstdint>

#define BATCH  4096
#define TSTEPS 100
#define DDIM   100
#define OOUT   3
#define CW     (BATCH * OOUT)

#define FPSCALE 67108864.0f                       /* 2^26 */
#define INV_FPSCALE 1.490116119384765625e-8f      /* 2^-26 */

#define ROWB   400                 /* bytes per 100-float row       */
#define RPC    4                   /* rows per chunk                */
#define NCHUNK (TSTEPS / RPC)      /* 25 chunks                     */
#define XBYTES (RPC * ROWB)        /* 1600 B x-part per chunk       */
#define CBYTES (2 * XBYTES)        /* 3200 B per ring slot (x + u)  */

__device__ __forceinline__ unsigned smem_u32(const void* p) {
    return (unsigned)__cvta_generic_to_shared(p);
}
__device__ __forceinline__ void mbar_init(unsigned mbar, unsigned cnt) {
    asm volatile("mbarrier.init.shared.b64 [%0], %1;" :: "r"(mbar), "r"(cnt) : "memory");
}
__device__ __forceinline__ void mbar_expect_tx(unsigned mbar, unsigned bytes) {
    asm volatile("mbarrier.arrive.expect_tx.shared.b64 _, [%0], %1;"
                 :: "r"(mbar), "r"(bytes) : "memory");
}
__device__ __forceinline__ void bulk_g2s(unsigned dst, const void* src,
                                         unsigned bytes, unsigned mbar) {
    asm volatile("cp.async.bulk.shared::cta.global.mbarrier::complete_tx::bytes "
                 "[%0], [%1], %2, [%3];"
                 :: "r"(dst), "l"(src), "r"(bytes), "r"(mbar) : "memory");
}
__device__ __forceinline__ void mbar_wait(unsigned mbar, unsigned parity) {
    asm volatile(
        "{\n\t.reg .pred P;\n\t"
        "WL%=:\n\t"
        "mbarrier.try_wait.parity.acquire.cta.shared::cta.b64 P, [%0], %1, 0x989680;\n\t"
        "@P bra WD%=;\n\t"
        "bra WL%=;\n\t"
        "WD%=:\n\t}"
        :: "r"(mbar), "r"(parity) : "memory");
}

// Warp = batch element (R12 frame). Inputs arrive via per-warp double-buffered
// cp.async.bulk ring (one 1600B bulk request per tensor per chunk of 4 rows).
// Compute: 4-bit mask -> smem LUT fixed-point subset sums -> REDUX.SUM per
// channel -> warp-local leaky scan; int math bit-identical to R12.
__global__ __launch_bounds__(128) void leaky_tma(
    const float* __restrict__ x, const float* __restrict__ u,
    const float* __restrict__ W, const float* __restrict__ bias,
    const float* __restrict__ betap, const float* __restrict__ thrp,
    float* __restrict__ out)
{
    __shared__ int4 lut[16 * 32];                         // 8 KB
    __shared__ __align__(16) char ring[4][2][CBYTES];     // 25.6 KB
    __shared__ unsigned long long mbar[4][2];             // 64 B

    // LUT[mask][lane] = fixed-point subset sums of lane's 4 weight columns
    for (int e = threadIdx.x; e < 16 * 32; e += 128) {
        const int mask = e >> 5;
        const int ln   = e & 31;
        int s0 = 0, s1 = 0, s2 = 0;
        if (ln < (DDIM / 4)) {
            #pragma unroll
            for (int bit = 0; bit < 4; ++bit) {
                if ((mask >> bit) & 1) {
                    const int col = ln * 4 + bit;
                    s0 += __float2int_rn(__ldg(W + 0 * DDIM + col) * FPSCALE);
                    s1 += __float2int_rn(__ldg(W + 1 * DDIM + col) * FPSCALE);
                    s2 += __float2int_rn(__ldg(W + 2 * DDIM + col) * FPSCALE);
                }
            }
        }
        lut[(mask << 5) | ln] = make_int4(s0, s1, s2, 0);
    }
    if (threadIdx.x == 0) {
        #pragma unroll
        for (int i = 0; i < 8; ++i)
            mbar_init(smem_u32(&mbar[i >> 1][i & 1]), 1);
        asm volatile("fence.proxy.async.shared::cta;" ::: "memory");
    }
    __syncthreads();

    const int wid  = threadIdx.x >> 5;
    const int lane = threadIdx.x & 31;
    const int gw   = (blockIdx.x << 2) | wid;   // batch id (grid exact)
    const bool act = (lane < (DDIM / 4));       // 25 consume lanes

    const float beta = __ldg(betap);
    const float thr  = __ldg(thrp);
    const float bl   = __ldg(bias + ((lane < 2) ? lane : 2));

    const char* __restrict__ xb = (const char*)(x + (size_t)gw * (TSTEPS * DDIM));
    const char* __restrict__ ub = (const char*)(u + (size_t)gw * (TSTEPS * DDIM));

    // prologue: fill both ring slots (chunks 0 and 1)
    if (lane == 0) {
        #pragma unroll
        for (int s = 0; s < 2; ++s) {
            const unsigned mb = smem_u32(&mbar[wid][s]);
            const unsigned d  = smem_u32(&ring[wid][s][0]);
            mbar_expect_tx(mb, CBYTES);
            bulk_g2s(d,          xb + s * XBYTES, XBYTES, mb);
            bulk_g2s(d + XBYTES, ub + s * XBYTES, XBYTES, mb);
        }
    }

    float* __restrict__ spk = out;
    float* __restrict__ mem = out + (size_t)TSTEPS * CW;

    float m = 0.f, rr = 0.f;   // lane's channel scan state

    for (int c = 0; c < NCHUNK; ++c) {
        const int slot = c & 1;
        const unsigned mb = smem_u32(&mbar[wid][slot]);
        mbar_wait(mb, (c >> 1) & 1);

        const char* base = ring[wid][slot];

        #pragma unroll
        for (int r = 0; r < RPC; ++r) {
            int mask = 0;
            if (act) {
                const float4 xv = *(const float4*)(base + r * ROWB + lane * 16);
                const float4 uv = *(const float4*)(base + XBYTES + r * ROWB + lane * 16);
                mask = (uv.x < xv.x) | ((uv.y < xv.y) << 1)
                     | ((uv.z < xv.z) << 2) | ((uv.w < xv.w) << 3);
            }
            const int4 lv = lut[(mask << 5) | lane];
            const int s0 = __reduce_add_sync(0xffffffffu, lv.x);
            const int s1 = __reduce_add_sync(0xffffffffu, lv.y);
            const int s2 = __reduce_add_sync(0xffffffffu, lv.z);

            const int iv = (lane == 0) ? s0 : ((lane == 1) ? s1 : s2);
            m = beta * m + ((float)iv * INV_FPSCALE + bl) - rr;
            const float sp = (m - thr > 0.f) ? 1.f : 0.f;
            rr = sp * thr;
            if (lane < OOUT) {
                const int t = c * RPC + r;
                const size_t o = (size_t)t * CW + (size_t)gw * OOUT + lane;
                __stcs(spk + o, sp);
                __stcs(mem + o, m);
            }
        }

        __syncwarp();   // all lanes done reading slot before overwrite

        if (lane == 0 && (c + 2) < NCHUNK) {
            const unsigned d = smem_u32(&ring[wid][slot][0]);
            mbar_expect_tx(mb, CBYTES);
            bulk_g2s(d,          xb + (c + 2) * XBYTES, XBYTES, mb);
            bulk_g2s(d + XBYTES, ub + (c + 2) * XBYTES, XBYTES, mb);
        }
    }
}

extern "C" void kernel_launch(void* const* d_in, const int* in_sizes, int n_in,
                              void* d_out, int out_size)
{
    const float* x    = (const float*)d_in[0];
    const float* u    = (const float*)d_in[1];
    const float* W    = (const float*)d_in[2];
    const float* bias = (const float*)d_in[3];
    const float* beta = (const float*)d_in[4];
    const float* thr  = (const float*)d_in[5];
    float* out = (float*)d_out;

    leaky_tma<<<BATCH / 4, 128>>>(x, u, W, bias, beta, thr, out);
}

// round 17
// speedup vs baseline: 1.3736x; 1.3736x over previous
#include <cuda_runtime.h>

#define BATCH  4096
#define TSTEPS 100
#define DDIM   100
#define OOUT   3
#define CW     (BATCH * OOUT)

#define FPSCALE 67108864.0f                       /* 2^26 */
#define INV_FPSCALE 1.490116119384765625e-8f      /* 2^-26 */

#define ROWB   400        /* bytes per 100-float row            */
#define PAIRB  1600       /* ring slot: x rows (800B) + u rows  */
#define NSLOT  3
#define NPAIRS 50

__device__ __forceinline__ void cp16(unsigned dst, const void* src) {
    asm volatile("cp.async.cg.shared.global [%0], [%1], 16;\n" :: "r"(dst), "l"(src));
}
__device__ __forceinline__ void cp_commit() {
    asm volatile("cp.async.commit_group;\n");
}
__device__ __forceinline__ void cp_wait2() {
    asm volatile("cp.async.wait_group 2;\n");
}

// R12 frame (reg double-pair P/Q, mask->LUT->REDUX int sums, warp-local scan,
// scattered .cs stores) with refills sourced from a per-warp 3-slot cp.async
// ring running 3-5 pairs ahead: +50% DRAM-facing bytes in flight, compute
// path unchanged -> outputs bit-identical to R12.
__global__ __launch_bounds__(128, 7) void leaky_hybrid(
    const float* __restrict__ x, const float* __restrict__ u,
    const float* __restrict__ W, const float* __restrict__ bias,
    const float* __restrict__ betap, const float* __restrict__ thrp,
    float* __restrict__ out)
{
    __shared__ int4 lut[16 * 32];                            // 8 KB
    __shared__ __align__(16) char ring[4][NSLOT][PAIRB];     // 19.2 KB

    for (int e = threadIdx.x; e < 16 * 32; e += 128) {
        const int mask = e >> 5;
        const int ln   = e & 31;
        int s0 = 0, s1 = 0, s2 = 0;
        if (ln < (DDIM / 4)) {
            #pragma unroll
            for (int bit = 0; bit < 4; ++bit) {
                if ((mask >> bit) & 1) {
                    const int col = ln * 4 + bit;
                    s0 += __float2int_rn(__ldg(W + 0 * DDIM + col) * FPSCALE);
                    s1 += __float2int_rn(__ldg(W + 1 * DDIM + col) * FPSCALE);
                    s2 += __float2int_rn(__ldg(W + 2 * DDIM + col) * FPSCALE);
                }
            }
        }
        lut[(mask << 5) | ln] = make_int4(s0, s1, s2, 0);
    }
    __syncthreads();

    const int wid  = threadIdx.x >> 5;
    const int lane = threadIdx.x & 31;
    const int gw   = (blockIdx.x << 2) | wid;   // batch id (grid exact)
    const bool act = (lane < (DDIM / 4));       // 25 active lanes

    const float beta = __ldg(betap);
    const float thr  = __ldg(thrp);
    const float bl   = __ldg(bias + ((lane < 2) ? lane : 2));

    const char* __restrict__ xb = (const char*)(x + (size_t)gw * (TSTEPS * DDIM));
    const char* __restrict__ ub = (const char*)(u + (size_t)gw * (TSTEPS * DDIM));
    const char* const myring = ring[wid][0];
    const unsigned rbase = (unsigned)__cvta_generic_to_shared(myring);
    const int loff = lane * 16;

    const float4 z = make_float4(0.f, 0.f, 0.f, 0.f);

    // prologue: pairs 0,1 straight to registers (.ca LDG, as in R12)
    float4 xp0 = z, up0 = z, xp1 = z, up1 = z;   // pair P
    float4 xq0 = z, uq0 = z, xq1 = z, uq1 = z;   // pair Q
    if (act) {
        const float4* xr = (const float4*)xb;
        const float4* ur = (const float4*)ub;
        xp0 = xr[lane];                  up0 = ur[lane];
        xp1 = xr[lane + 25];             up1 = ur[lane + 25];
        xq0 = xr[lane + 50];             uq0 = ur[lane + 50];
        xq1 = xr[lane + 75];             uq1 = ur[lane + 75];
    }
    // pairs 2,3,4 -> ring slots 0,1,2 (one commit each)
    #pragma unroll
    for (int k = 2; k <= 4; ++k) {
        if (act) {
            const unsigned d = rbase + (k - 2) * PAIRB + loff;
            const int r = 2 * k;
            cp16(d,            xb + (r + 0) * ROWB + loff);
            cp16(d + ROWB,     xb + (r + 1) * ROWB + loff);
            cp16(d + 2 * ROWB, ub + (r + 0) * ROWB + loff);
            cp16(d + 3 * ROWB, ub + (r + 1) * ROWB + loff);
        }
        cp_commit();
    }

    float* __restrict__ spk = out;
    float* __restrict__ mem = out + (size_t)TSTEPS * CW;

    float m = 0.f, rr = 0.f;
    int sa = 0, sb = 1;   // ring slots of pairs 2i+2 and 2i+3

    for (int i = 0; i < 25; ++i) {
        // ================= stage A: process pair 2i (rows 4i, 4i+1) =========
        {
            const int ma = (up0.x < xp0.x) | ((up0.y < xp0.y) << 1)
                         | ((up0.z < xp0.z) << 2) | ((up0.w < xp0.w) << 3);
            const int mb = (up1.x < xp1.x) | ((up1.y < xp1.y) << 1)
                         | ((up1.z < xp1.z) << 2) | ((up1.w < xp1.w) << 3);

            cp_wait2();   // pair 2i+2 resident in slot sa
            if (act && (2 * i + 2) < NPAIRS) {   // LDS refill P <- pair 2i+2
                const char* s = myring + sa * PAIRB + loff;
                xp0 = *(const float4*)(s);
                xp1 = *(const float4*)(s + ROWB);
                up0 = *(const float4*)(s + 2 * ROWB);
                up1 = *(const float4*)(s + 3 * ROWB);
            }
            if (act && (2 * i + 5) < NPAIRS) {   // refill slot sa <- pair 2i+5
                const unsigned d = rbase + sa * PAIRB + loff;
                const int r = 2 * (2 * i + 5);
                cp16(d,            xb + (r + 0) * ROWB + loff);
                cp16(d + ROWB,     xb + (r + 1) * ROWB + loff);
                cp16(d + 2 * ROWB, ub + (r + 0) * ROWB + loff);
                cp16(d + 3 * ROWB, ub + (r + 1) * ROWB + loff);
            }
            cp_commit();   // always: FIFO group alignment

            const int4 la = lut[(ma << 5) | lane];
            const int4 lb = lut[(mb << 5) | lane];
            const int s0a = __reduce_add_sync(0xffffffffu, la.x);
            const int s0b = __reduce_add_sync(0xffffffffu, lb.x);
            const int s1a = __reduce_add_sync(0xffffffffu, la.y);
            const int s1b = __reduce_add_sync(0xffffffffu, lb.y);
            const int s2a = __reduce_add_sync(0xffffffffu, la.z);
            const int s2b = __reduce_add_sync(0xffffffffu, lb.z);

            const int ia = (lane == 0) ? s0a : ((lane == 1) ? s1a : s2a);
            const int ib = (lane == 0) ? s0b : ((lane == 1) ? s1b : s2b);

            const int t = 4 * i;
            m = beta * m + ((float)ia * INV_FPSCALE + bl) - rr;
            float sp = (m - thr > 0.f) ? 1.f : 0.f;
            rr = sp * thr;
            if (lane < OOUT) {
                const size_t o = (size_t)t * CW + (size_t)gw * OOUT + lane;
                __stcs(spk + o, sp); __stcs(mem + o, m);
            }
            m = beta * m + ((float)ib * INV_FPSCALE + bl) - rr;
            sp = (m - thr > 0.f) ? 1.f : 0.f;
            rr = sp * thr;
            if (lane < OOUT) {
                const size_t o = (size_t)(t + 1) * CW + (size_t)gw * OOUT + lane;
                __stcs(spk + o, sp); __stcs(mem + o, m);
            }
            sa = (sa + 2 >= NSLOT) ? sa - 1 : sa + 2;
        }
        // ================= stage B: process pair 2i+1 (rows 4i+2, 4i+3) =====
        {
            const int ma = (uq0.x < xq0.x) | ((uq0.y < xq0.y) << 1)
                         | ((uq0.z < xq0.z) << 2) | ((uq0.w < xq0.w) << 3);
            const int mb = (uq1.x < xq1.x) | ((uq1.y < xq1.y) << 1)
                         | ((uq1.z < xq1.z) << 2) | ((uq1.w < xq1.w) << 3);

            cp_wait2();   // pair 2i+3 resident in slot sb
            if (act && (2 * i + 3) < NPAIRS) {   // LDS refill Q <- pair 2i+3
                const char* s = myring + sb * PAIRB + loff;
                xq0 = *(const float4*)(s);
                xq1 = *(const float4*)(s + ROWB);
                uq0 = *(const float4*)(s + 2 * ROWB);
                uq1 = *(const float4*)(s + 3 * ROWB);
            }
            if (act && (2 * i + 6) < NPAIRS) {   // refill slot sb <- pair 2i+6
                const unsigned d = rbase + sb * PAIRB + loff;
                const int r = 2 * (2 * i + 6);
                cp16(d,            xb + (r + 0) * ROWB + loff);
                cp16(d + ROWB,     xb + (r + 1) * ROWB + loff);
                cp16(d + 2 * ROWB, ub + (r + 0) * ROWB + loff);
                cp16(d + 3 * ROWB, ub + (r + 1) * ROWB + loff);
            }
            cp_commit();

            const int4 la = lut[(ma << 5) | lane];
            const int4 lb = lut[(mb << 5) | lane];
            const int s0a = __reduce_add_sync(0xffffffffu, la.x);
            const int s0b = __reduce_add_sync(0xffffffffu, lb.x);
            const int s1a = __reduce_add_sync(0xffffffffu, la.y);
            const int s1b = __reduce_add_sync(0xffffffffu, lb.y);
            const int s2a = __reduce_add_sync(0xffffffffu, la.z);
            const int s2b = __reduce_add_sync(0xffffffffu, lb.z);

            const int ia = (lane == 0) ? s0a : ((lane == 1) ? s1a : s2a);
            const int ib = (lane == 0) ? s0b : ((lane == 1) ? s1b : s2b);

            const int t = 4 * i + 2;
            m = beta * m + ((float)ia * INV_FPSCALE + bl) - rr;
            float sp = (m - thr > 0.f) ? 1.f : 0.f;
            rr = sp * thr;
            if (lane < OOUT) {
                const size_t o = (size_t)t * CW + (size_t)gw * OOUT + lane;
                __stcs(spk + o, sp); __stcs(mem + o, m);
            }
            m = beta * m + ((float)ib * INV_FPSCALE + bl) - rr;
            sp = (m - thr > 0.f) ? 1.f : 0.f;
            rr = sp * thr;
            if (lane < OOUT) {
                const size_t o = (size_t)(t + 1) * CW + (size_t)gw * OOUT + lane;
                __stcs(spk + o, sp); __stcs(mem + o, m);
            }
            sb = (sb + 2 >= NSLOT) ? sb - 1 : sb + 2;
        }
    }
}

extern "C" void kernel_launch(void* const* d_in, const int* in_sizes, int n_in,
                              void* d_out, int out_size)
{
    const float* x    = (const float*)d_in[0];
    const float* u    = (const float*)d_in[1];
    const float* W    = (const float*)d_in[2];
    const float* bias = (const float*)d_in[3];
    const float* beta = (const float*)d_in[4];
    const float* thr  = (const float*)d_in[5];
    float* out = (float*)d_out;

    leaky_hybrid<<<BATCH / 4, 128>>>(x, u, W, bias, beta, thr, out);
}